// round 14
// baseline (speedup 1.0000x reference)
#include <cuda_runtime.h>
#include <cuda_bf16.h>
#include <math.h>
#include <stdint.h>

// ---------------- problem constants ----------------
#define BNUM 32
#define HH   56
#define WW   56
#define CC   192
#define NHH  6
#define HD   32
#define WSZ  7
#define SSZ  3
#define NN   49
#define NWIN 64
#define TOK  (BNUM*HH*WW)   // 100352
#define HIDD 768

typedef __nv_bfloat16 bf16;

// ---------------- scratch ----------------
__device__ bf16  g_xw  [(size_t)TOK*CC];
__device__ bf16  g_qkv [(size_t)TOK*3*CC];
__device__ bf16  g_attn[(size_t)TOK*CC];
__device__ float g_y   [(size_t)TOK*CC];
__device__ bf16  g_xm  [(size_t)TOK*CC];
__device__ bf16  g_h   [(size_t)TOK*HIDD];
__device__ float g_tab [4*6*49*64];
__device__ bf16  g_wqkv[(size_t)576*192];
__device__ bf16  g_wprj[(size_t)192*192];
__device__ bf16  g_wfc1[(size_t)HIDD*192];
__device__ bf16  g_wfc2[(size_t)192*HIDD];

// ---------------- PTX helpers ----------------
__device__ __forceinline__ uint32_t smem_u32(const void* p) {
    uint32_t a;
    asm("{ .reg .u64 t; cvta.to.shared.u64 t, %1; cvt.u32.u64 %0, t; }"
        : "=r"(a) : "l"(p));
    return a;
}
__device__ __forceinline__ void cp16(uint32_t s, const void* g) {
    asm volatile("cp.async.cg.shared.global [%0], [%1], 16;" :: "r"(s), "l"(g));
}
#define CP_COMMIT() asm volatile("cp.async.commit_group;" ::: "memory")
__device__ __forceinline__ void ldsm4(uint32_t& r0, uint32_t& r1, uint32_t& r2,
                                      uint32_t& r3, uint32_t a) {
    asm volatile("ldmatrix.sync.aligned.m8n8.x4.shared.b16 {%0,%1,%2,%3}, [%4];"
                 : "=r"(r0), "=r"(r1), "=r"(r2), "=r"(r3) : "r"(a));
}
__device__ __forceinline__ void ldsm4t(uint32_t& r0, uint32_t& r1, uint32_t& r2,
                                       uint32_t& r3, uint32_t a) {
    asm volatile("ldmatrix.sync.aligned.m8n8.x4.trans.shared.b16 {%0,%1,%2,%3}, [%4];"
                 : "=r"(r0), "=r"(r1), "=r"(r2), "=r"(r3) : "r"(a));
}
__device__ __forceinline__ void mma_bf16(float* c, const uint32_t* a, const uint32_t* b) {
    asm volatile(
        "mma.sync.aligned.m16n8k16.row.col.f32.bf16.bf16.f32 "
        "{%0,%1,%2,%3}, {%4,%5,%6,%7}, {%8,%9}, {%0,%1,%2,%3};"
        : "+f"(c[0]), "+f"(c[1]), "+f"(c[2]), "+f"(c[3])
        : "r"(a[0]), "r"(a[1]), "r"(a[2]), "r"(a[3]), "r"(b[0]), "r"(b[1]));
}
__device__ __forceinline__ uint32_t packbf2(float lo, float hi) {
    __nv_bfloat162 h2 = __floats2bfloat162_rn(lo, hi);
    return *reinterpret_cast<uint32_t*>(&h2);
}

// ============ merged prep: 4 weight transposes + bias/mask tables =========
__device__ __forceinline__ void wtrans_tile(const float* W, bf16* Wt,
                                            int K, int N, int bx, int by, int t)
{
    __shared__ float tile[32][33];
    int k0 = by * 32, n0 = bx * 32;
    int tx = t & 31, ty = t >> 5;   // 32 x 8
#pragma unroll
    for (int i = 0; i < 32; i += 8)
        tile[ty + i][tx] = W[(size_t)(k0 + ty + i) * N + n0 + tx];
    __syncthreads();
#pragma unroll
    for (int i = 0; i < 32; i += 8)
        Wt[(size_t)(n0 + ty + i) * K + k0 + tx] = __float2bfloat16(tile[tx][ty + i]);
}

__global__ void prep_kernel(const float* __restrict__ qkv_w,
                            const float* __restrict__ proj_w,
                            const float* __restrict__ fc1_w,
                            const float* __restrict__ fc2_w,
                            const float* __restrict__ rel_bias)
{
    const int b = blockIdx.x;
    const int t = threadIdx.x;
    if (b < 108) {
        wtrans_tile(qkv_w, g_wqkv, CC, 3 * CC, b % 18, b / 18, t);
    } else if (b < 144) {
        int bb = b - 108;
        wtrans_tile(proj_w, g_wprj, CC, CC, bb % 6, bb / 6, t);
    } else if (b < 288) {
        int bb = b - 144;
        wtrans_tile(fc1_w, g_wfc1, CC, HIDD, bb % 24, bb / 24, t);
    } else if (b < 432) {
        int bb = b - 288;
        wtrans_tile(fc2_w, g_wfc2, HIDD, CC, bb % 6, bb / 6, t);
    } else {
        int bh = b - 432;             // 0..23 = mi*6 + h
        int mi = bh / 6, h = bh % 6;
        int eh = mi >> 1, ew = mi & 1;
        for (int idx = t; idx < NN * 64; idx += 256) {
            int i = idx >> 6, j = idx & 63;
            float val;
            if (j >= NN) val = -1e30f;
            else {
                int ih = i / WSZ, iw = i % WSZ, jh = j / WSZ, jw = j % WSZ;
                int dh = ih - jh + (WSZ - 1), dw = iw - jw + (WSZ - 1);
                float bias = rel_bias[(dh * (2 * WSZ - 1) + dw) * NHH + h];
                int ai = eh ? (ih < WSZ - SSZ ? 1 : 2) : 0;
                int bi = ew ? (iw < WSZ - SSZ ? 1 : 2) : 0;
                int aj = eh ? (jh < WSZ - SSZ ? 1 : 2) : 0;
                int bj = ew ? (jw < WSZ - SSZ ? 1 : 2) : 0;
                float mask = ((ai * 3 + bi) != (aj * 3 + bj)) ? -100.0f : 0.0f;
                val = bias + mask;
            }
            g_tab[(size_t)bh * (NN * 64) + idx] = val;
        }
    }
}

// ---------------- LayerNorm (warp per token), bf16 output -----------------
template<int MODE>
__global__ void ln_kernel(const float* __restrict__ x,
                          const float* __restrict__ gamma,
                          const float* __restrict__ beta)
{
    int warp = (blockIdx.x * blockDim.x + threadIdx.x) >> 5;
    int lane = threadIdx.x & 31;
    if (warp >= TOK) return;

    const float* src;
    bf16* dst;
    if (MODE == 0) {
        int tw = warp;
        int w  = tw / NN, n = tw % NN;
        int bb = w / NWIN, wi = w % NWIN;
        int wrow = wi >> 3, wcol = wi & 7;
        int ih = n / WSZ, iw = n % WSZ;
        int gh = wrow * WSZ + ih + SSZ; if (gh >= HH) gh -= HH;
        int gw = wcol * WSZ + iw + SSZ; if (gw >= WW) gw -= WW;
        src = x + ((size_t)bb * HH * WW + (size_t)gh * WW + gw) * CC;
        dst = g_xw + (size_t)tw * CC;
    } else {
        src = g_y + (size_t)warp * CC;
        dst = g_xm + (size_t)warp * CC;
    }

    float v[6];
    float s = 0.f;
#pragma unroll
    for (int k = 0; k < 6; k++) { v[k] = src[lane + 32 * k]; s += v[k]; }
#pragma unroll
    for (int o = 16; o; o >>= 1) s += __shfl_xor_sync(0xffffffffu, s, o);
    float mean = s * (1.0f / CC);
    float vs = 0.f;
#pragma unroll
    for (int k = 0; k < 6; k++) { float d = v[k] - mean; vs += d * d; }
#pragma unroll
    for (int o = 16; o; o >>= 1) vs += __shfl_xor_sync(0xffffffffu, vs, o);
    float inv = rsqrtf(vs * (1.0f / CC) + 1e-5f);
#pragma unroll
    for (int k = 0; k < 6; k++) {
        int c = lane + 32 * k;
        dst[c] = __float2bfloat16((v[k] - mean) * inv * gamma[c] + beta[c]);
    }
}

// ================= bf16 mma GEMM (round-13 proven config) =================
// BM=128, BN=64, BK=64. 128 threads = 4 warps (4m x 1n), warp tile 32x64.
// 2-stage cp.async double buffer, dynamic smem (55.3 KB).
#define SRB   144                       // smem row bytes
#define A_STG_B (128 * SRB)             // 18432
#define B_STG_B (64  * SRB)             // 9216
#define G_SMEM  (2 * (A_STG_B + B_STG_B))   // 55296

template<int ACT, int RESM, bool OBF>
__global__ void __launch_bounds__(128)
gemm_bf16(const bf16* __restrict__ A, const bf16* __restrict__ Wt,
          const float* __restrict__ bias, const float* __restrict__ res,
          void* __restrict__ Cv, int M, int N, int K)
{
    extern __shared__ __align__(16) char smem[];
    const uint32_t asB = smem_u32(smem);
    const uint32_t bsB = asB + 2 * A_STG_B;

    const int t    = threadIdx.x;
    const int lane = t & 31;
    const int wid  = t >> 5;
    const int m0   = blockIdx.y << 7;
    const int n0   = blockIdx.x << 6;

    const int T = K >> 6;

    auto load_tiles = [&](int kt, int b) {
        const int k0 = kt << 6;
        uint32_t aD = asB + b * A_STG_B;
#pragma unroll
        for (int r = 0; r < 8; r++) {
            int i = t + 128 * r;
            int row = i >> 3, c = i & 7;
            cp16(aD + row * SRB + (c << 4),
                 A + (size_t)(m0 + row) * K + k0 + (c << 3));
        }
        uint32_t bD = bsB + b * B_STG_B;
#pragma unroll
        for (int r = 0; r < 4; r++) {
            int i = t + 128 * r;
            int row = i >> 3, c = i & 7;
            cp16(bD + row * SRB + (c << 4),
                 Wt + (size_t)(n0 + row) * K + k0 + (c << 3));
        }
        CP_COMMIT();
    };

    float acc[2][8][4];
#pragma unroll
    for (int i = 0; i < 2; i++)
#pragma unroll
        for (int j = 0; j < 8; j++)
#pragma unroll
            for (int q = 0; q < 4; q++) acc[i][j][q] = 0.f;

    const uint32_t aFrag = (wid * 32 + (lane & 15)) * SRB + ((lane >> 4) << 4);
    const uint32_t bFrag = ((lane & 7) + (((lane >> 4) & 1) << 3)) * SRB
                           + (((lane >> 3) & 1) << 4);

    load_tiles(0, 0);

    for (int kt = 0; kt < T; kt++) {
        const int b = kt & 1;
        if (kt + 1 < T) {
            load_tiles(kt + 1, b ^ 1);
            asm volatile("cp.async.wait_group 1;" ::: "memory");
        } else {
            asm volatile("cp.async.wait_group 0;" ::: "memory");
        }
        __syncthreads();

        const uint32_t aB = asB + b * A_STG_B + aFrag;
        const uint32_t bB = bsB + b * B_STG_B + bFrag;
#pragma unroll
        for (int kk = 0; kk < 4; kk++) {
            uint32_t av[2][4], bv[8][2];
            ldsm4(av[0][0], av[0][1], av[0][2], av[0][3], aB + kk * 32);
            ldsm4(av[1][0], av[1][1], av[1][2], av[1][3], aB + 16 * SRB + kk * 32);
#pragma unroll
            for (int g = 0; g < 4; g++)
                ldsm4(bv[2 * g][0], bv[2 * g][1], bv[2 * g + 1][0], bv[2 * g + 1][1],
                      bB + g * 16 * SRB + kk * 32);
#pragma unroll
            for (int mt = 0; mt < 2; mt++)
#pragma unroll
                for (int nt = 0; nt < 8; nt++)
                    mma_bf16(acc[mt][nt], av[mt], bv[nt]);
        }
        __syncthreads();
    }

    // ---------------- epilogue ----------------
    const int colBase = n0 + ((lane & 3) << 1);
    const int rowBase = m0 + wid * 32 + (lane >> 2);
#pragma unroll
    for (int mt = 0; mt < 2; mt++) {
#pragma unroll
        for (int half = 0; half < 2; half++) {
            const int r = rowBase + mt * 16 + half * 8;
            size_t outRow = (size_t)r;
            if (RESM == 2) {
                int wq = r / NN, nq = r % NN;
                int bq = wq >> 6, wiq = wq & 63;
                int gh = (wiq >> 3) * WSZ + nq / WSZ + SSZ; if (gh >= HH) gh -= HH;
                int gw = (wiq & 7)  * WSZ + nq % WSZ + SSZ; if (gw >= WW) gw -= WW;
                outRow = (size_t)bq * (HH * WW) + gh * WW + gw;
            }
            const float* Rrow = res + outRow * N;
#pragma unroll
            for (int nt = 0; nt < 8; nt++) {
                const int c0 = colBase + nt * 8;
                float v0 = acc[mt][nt][half * 2 + 0] + bias[c0];
                float v1 = acc[mt][nt][half * 2 + 1] + bias[c0 + 1];
                if (ACT == 1) {
                    v0 = 0.5f * v0 * (1.0f + erff(v0 * 0.70710678118654752f));
                    v1 = 0.5f * v1 * (1.0f + erff(v1 * 0.70710678118654752f));
                }
                if (RESM != 0) { v0 += Rrow[c0]; v1 += Rrow[c0 + 1]; }
                if (OBF) {
                    bf16* Crow = (bf16*)Cv + outRow * N;
                    *(__nv_bfloat162*)&Crow[c0] = __floats2bfloat162_rn(v0, v1);
                } else {
                    float* Crow = (float*)Cv + outRow * N;
                    float2 o; o.x = v0; o.y = v1;
                    *(float2*)&Crow[c0] = o;
                }
            }
        }
    }
}

// ======= tensor-core windowed attention: 1 block/window, 3 head-pairs =====
// 256 threads = 8 warps. Warps 0-3 -> even head, 4-7 -> odd head of the pair.
// Double-buffered QKV smem across head-pairs: prefetch hp+1 during compute hp.
// smem: Q[2buf][2head], K..., V... : 3 * 2 * 2 * 5120 B = 61440 B (dynamic).
#define SROW 40
#define AH_B  5120                      // one head tile: 64 rows * 80 B
#define ATT_SMEM (3 * 2 * 2 * AH_B)     // 61440

__global__ void __launch_bounds__(256)
attn_mma_kernel()
{
    extern __shared__ __align__(16) char asmem[];
    const uint32_t qBase = smem_u32(asmem);
    const uint32_t kBase = qBase + 4 * AH_B;
    const uint32_t vBase = qBase + 8 * AH_B;

    const int w = blockIdx.x;            // window 0..2047
    const int t = threadIdx.x;
    const int lane = t & 31;
    const int wid = t >> 5;
    const int hs  = wid >> 2;            // head within pair
    const int mt  = wid & 3;             // m-tile within head

    // zero padding rows 49..63 for all 4 (buf, head) tiles of each tensor
    for (int i = t; i < 4 * 15 * 20; i += 256) {
        int sel = i / 300, j = i % 300;
        uint32_t off = sel * (AH_B / 4) + (49 + j / 20) * 20 + (j % 20);
        ((uint32_t*)asmem)[off] = 0;
        ((uint32_t*)asmem)[off + 4 * (AH_B / 4)] = 0;
        ((uint32_t*)asmem)[off + 8 * (AH_B / 4)] = 0;
    }

    const bf16* wbase = g_qkv + (size_t)w * NN * (3 * CC);
    auto prefetch = [&](int hp, int b) {
        // 2 heads x 49 rows x 4 chunks of 16B per tensor
        for (int i = t; i < 2 * NN * 4; i += 256) {
            int hsel = i / (NN * 4), j = i % (NN * 4);
            int r = j >> 2, c = (j & 3) << 3;
            const bf16* src = wbase + (size_t)r * (3 * CC) + (hp * 2 + hsel) * HD + c;
            uint32_t d = (b * 2 + hsel) * AH_B + r * 80 + (c << 1);
            cp16(qBase + d, src);
            cp16(kBase + d, src + CC);
            cp16(vBase + d, src + 2 * CC);
        }
        CP_COMMIT();
    };

    // window edge class (constant over hp)
    const int wi = w & (NWIN - 1);
    const int mi = (((wi >> 3) == 7) ? 2 : 0) + (((wi & 7) == 7) ? 1 : 0);
    const int r0 = mt * 16 + (lane >> 2);
    const float scale = 0.17677669529663687f;

    const uint32_t aOff = (mt * 16 + (lane & 15)) * 80 + ((lane >> 4) << 4);
    const uint32_t bOff = ((lane & 7) + (((lane >> 4) & 1) << 3)) * 80
                          + (((lane >> 3) & 1) << 4);
    const uint32_t vOff = ((((lane >> 3) & 1) << 3) + (lane & 7)) * 80
                          + (((lane >> 4) & 1) << 4);

    prefetch(0, 0);

    for (int hp = 0; hp < 3; hp++) {
        const int b = hp & 1;
        if (hp + 1 < 3) {
            prefetch(hp + 1, b ^ 1);
            asm volatile("cp.async.wait_group 1;" ::: "memory");
        } else {
            asm volatile("cp.async.wait_group 0;" ::: "memory");
        }
        __syncthreads();

        const int h = hp * 2 + hs;
        const uint32_t tOff = (b * 2 + hs) * AH_B;
        const uint32_t qB = qBase + tOff, kB = kBase + tOff, vB = vBase + tOff;

        // ---- S = Q K^T ----
        float sacc[8][4];
#pragma unroll
        for (int i = 0; i < 8; i++)
#pragma unroll
            for (int q = 0; q < 4; q++) sacc[i][q] = 0.f;

        const uint32_t aAddr = qB + aOff;
        const uint32_t bAddr = kB + bOff;
#pragma unroll
        for (int kk = 0; kk < 2; kk++) {
            uint32_t av[4];
            ldsm4(av[0], av[1], av[2], av[3], aAddr + kk * 32);
#pragma unroll
            for (int ng = 0; ng < 4; ng++) {
                uint32_t b0, b1, b2, b3;
                ldsm4(b0, b1, b2, b3, bAddr + ng * 16 * 80 + kk * 32);
                uint32_t bv0[2] = {b0, b1}, bv1[2] = {b2, b3};
                mma_bf16(sacc[2 * ng],     av, bv0);
                mma_bf16(sacc[2 * ng + 1], av, bv1);
            }
        }

        // ---- scale + table + softmax in fragments ----
        const float* tb = g_tab + (size_t)(mi * NHH + h) * (NN * 64);
#pragma unroll
        for (int nt = 0; nt < 8; nt++) {
            const int c = nt * 8 + ((lane & 3) << 1);
            float t00 = 0.f, t01 = 0.f, t10 = 0.f, t11 = 0.f;
            if (r0 < NN)     { float2 tt = *(const float2*)&tb[r0 * 64 + c];      t00 = tt.x; t01 = tt.y; }
            if (r0 + 8 < NN) { float2 tt = *(const float2*)&tb[(r0 + 8) * 64 + c]; t10 = tt.x; t11 = tt.y; }
            sacc[nt][0] = sacc[nt][0] * scale + t00;
            sacc[nt][1] = sacc[nt][1] * scale + t01;
            sacc[nt][2] = sacc[nt][2] * scale + t10;
            sacc[nt][3] = sacc[nt][3] * scale + t11;
        }

        float m0 = -1e30f, m1 = -1e30f;
#pragma unroll
        for (int nt = 0; nt < 8; nt++) {
            m0 = fmaxf(m0, fmaxf(sacc[nt][0], sacc[nt][1]));
            m1 = fmaxf(m1, fmaxf(sacc[nt][2], sacc[nt][3]));
        }
        m0 = fmaxf(m0, __shfl_xor_sync(0xffffffffu, m0, 1));
        m0 = fmaxf(m0, __shfl_xor_sync(0xffffffffu, m0, 2));
        m1 = fmaxf(m1, __shfl_xor_sync(0xffffffffu, m1, 1));
        m1 = fmaxf(m1, __shfl_xor_sync(0xffffffffu, m1, 2));

        float s0 = 0.f, s1 = 0.f;
#pragma unroll
        for (int nt = 0; nt < 8; nt++) {
            sacc[nt][0] = __expf(sacc[nt][0] - m0);
            sacc[nt][1] = __expf(sacc[nt][1] - m0);
            sacc[nt][2] = __expf(sacc[nt][2] - m1);
            sacc[nt][3] = __expf(sacc[nt][3] - m1);
            s0 += sacc[nt][0] + sacc[nt][1];
            s1 += sacc[nt][2] + sacc[nt][3];
        }
        s0 += __shfl_xor_sync(0xffffffffu, s0, 1);
        s0 += __shfl_xor_sync(0xffffffffu, s0, 2);
        s1 += __shfl_xor_sync(0xffffffffu, s1, 1);
        s1 += __shfl_xor_sync(0xffffffffu, s1, 2);
        const float i0 = 1.0f / s0, i1 = 1.0f / s1;

        // ---- O = P V ----
        float oacc[4][4];
#pragma unroll
        for (int i = 0; i < 4; i++)
#pragma unroll
            for (int q = 0; q < 4; q++) oacc[i][q] = 0.f;

        const uint32_t vAddr = vB + vOff;
#pragma unroll
        for (int kk = 0; kk < 4; kk++) {
            uint32_t pa[4];
            pa[0] = packbf2(sacc[2 * kk][0] * i0,     sacc[2 * kk][1] * i0);
            pa[1] = packbf2(sacc[2 * kk][2] * i1,     sacc[2 * kk][3] * i1);
            pa[2] = packbf2(sacc[2 * kk + 1][0] * i0, sacc[2 * kk + 1][1] * i0);
            pa[3] = packbf2(sacc[2 * kk + 1][2] * i1, sacc[2 * kk + 1][3] * i1);
            uint32_t b0, b1, b2, b3;
            ldsm4t(b0, b1, b2, b3, vAddr + kk * 16 * 80);
            { uint32_t bv0[2] = {b0, b1}, bv1[2] = {b2, b3};
              mma_bf16(oacc[0], pa, bv0); mma_bf16(oacc[1], pa, bv1); }
            ldsm4t(b0, b1, b2, b3, vAddr + kk * 16 * 80 + 32);
            { uint32_t bv0[2] = {b0, b1}, bv1[2] = {b2, b3};
              mma_bf16(oacc[2], pa, bv0); mma_bf16(oacc[3], pa, bv1); }
        }

        bf16* outB = g_attn + (size_t)w * NN * CC + h * HD;
#pragma unroll
        for (int nt = 0; nt < 4; nt++) {
            const int c = nt * 8 + ((lane & 3) << 1);
            if (r0 < NN)
                *(__nv_bfloat162*)&outB[(size_t)r0 * CC + c] =
                    __floats2bfloat162_rn(oacc[nt][0], oacc[nt][1]);
            if (r0 + 8 < NN)
                *(__nv_bfloat162*)&outB[(size_t)(r0 + 8) * CC + c] =
                    __floats2bfloat162_rn(oacc[nt][2], oacc[nt][3]);
        }
        __syncthreads();   // all reads of buffer b done before next prefetch overwrites it
    }
}

// ---------------- launch ----------------
extern "C" void kernel_launch(void* const* d_in, const int* in_sizes, int n_in,
                              void* d_out, int out_size)
{
    const float* x       = (const float*)d_in[0];
    const float* norm1_g = (const float*)d_in[1];
    const float* norm1_b = (const float*)d_in[2];
    const float* qkv_w   = (const float*)d_in[3];
    const float* qkv_b   = (const float*)d_in[4];
    const float* rel_b   = (const float*)d_in[5];
    const float* proj_w  = (const float*)d_in[6];
    const float* proj_b  = (const float*)d_in[7];
    const float* norm2_g = (const float*)d_in[8];
    const float* norm2_b = (const float*)d_in[9];
    const float* fc1_w   = (const float*)d_in[10];
    const float* fc1_b   = (const float*)d_in[11];
    const float* fc2_w   = (const float*)d_in[12];
    const float* fc2_b   = (const float*)d_in[13];
    float* out = (float*)d_out;

    bf16 *p_xw, *p_qkv, *p_attn, *p_xm, *p_h, *p_wqkv, *p_wprj, *p_wfc1, *p_wfc2;
    float *p_y;
    cudaGetSymbolAddress((void**)&p_xw,   g_xw);
    cudaGetSymbolAddress((void**)&p_qkv,  g_qkv);
    cudaGetSymbolAddress((void**)&p_attn, g_attn);
    cudaGetSymbolAddress((void**)&p_y,    g_y);
    cudaGetSymbolAddress((void**)&p_xm,   g_xm);
    cudaGetSymbolAddress((void**)&p_h,    g_h);
    cudaGetSymbolAddress((void**)&p_wqkv, g_wqkv);
    cudaGetSymbolAddress((void**)&p_wprj, g_wprj);
    cudaGetSymbolAddress((void**)&p_wfc1, g_wfc1);
    cudaGetSymbolAddress((void**)&p_wfc2, g_wfc2);

    cudaFuncSetAttribute(gemm_bf16<0, 0, true>,  cudaFuncAttributeMaxDynamicSharedMemorySize, G_SMEM);
    cudaFuncSetAttribute(gemm_bf16<0, 2, false>, cudaFuncAttributeMaxDynamicSharedMemorySize, G_SMEM);
    cudaFuncSetAttribute(gemm_bf16<1, 0, true>,  cudaFuncAttributeMaxDynamicSharedMemorySize, G_SMEM);
    cudaFuncSetAttribute(gemm_bf16<0, 1, false>, cudaFuncAttributeMaxDynamicSharedMemorySize, G_SMEM);
    cudaFuncSetAttribute(attn_mma_kernel, cudaFuncAttributeMaxDynamicSharedMemorySize, ATT_SMEM);

    const int lnBlocks = TOK / 8;

    // 0) merged prep
    prep_kernel<<<456, 256>>>(qkv_w, proj_w, fc1_w, fc2_w, rel_b);

    // 1) LN1 + shift + window partition (bf16)
    ln_kernel<0><<<lnBlocks, 256>>>(x, norm1_g, norm1_b);

    // 2) QKV gemm [TOK,192]x[192,576] -> bf16
    gemm_bf16<0, 0, true><<<dim3(576 / 64, TOK / 128), 128, G_SMEM>>>(
        p_xw, p_wqkv, qkv_b, nullptr, p_qkv, TOK, 3 * CC, CC);

    // 3) tensor-core windowed attention (1 block / window, 3 head-pairs)
    attn_mma_kernel<<<TOK / NN, 256, ATT_SMEM>>>();

    // 4) proj gemm + window-reverse/unshift scatter + residual -> g_y (fp32)
    gemm_bf16<0, 2, false><<<dim3(192 / 64, TOK / 128), 128, G_SMEM>>>(
        p_attn, p_wprj, proj_b, x, p_y, TOK, CC, CC);

    // 5) LN2 (bf16)
    ln_kernel<1><<<lnBlocks, 256>>>(nullptr, norm2_g, norm2_b);

    // 6) fc1 + exact GELU [TOK,192]x[192,768] -> bf16
    gemm_bf16<1, 0, true><<<dim3(HIDD / 64, TOK / 128), 128, G_SMEM>>>(
        p_xm, p_wfc1, fc1_b, nullptr, p_h, TOK, HIDD, CC);

    // 7) fc2 + residual [TOK,768]x[768,192] -> d_out (fp32)
    gemm_bf16<0, 1, false><<<dim3(192 / 64, TOK / 128), 128, G_SMEM>>>(
        p_h, p_wfc2, fc2_b, p_y, out, TOK, CC, HIDD);
}

// round 15
// speedup vs baseline: 1.0292x; 1.0292x over previous
#include <cuda_runtime.h>
#include <cuda_bf16.h>
#include <math.h>
#include <stdint.h>

// ---------------- problem constants ----------------
#define BNUM 32
#define HH   56
#define WW   56
#define CC   192
#define NHH  6
#define HD   32
#define WSZ  7
#define SSZ  3
#define NN   49
#define NWIN 64
#define TOK  (BNUM*HH*WW)   // 100352
#define HIDD 768

typedef __nv_bfloat16 bf16;

// ---------------- scratch ----------------
__device__ bf16  g_xw  [(size_t)TOK*CC];
__device__ bf16  g_qkv [(size_t)TOK*3*CC];
__device__ bf16  g_attn[(size_t)TOK*CC];
__device__ float g_y   [(size_t)TOK*CC];
__device__ bf16  g_xm  [(size_t)TOK*CC];
__device__ bf16  g_h   [(size_t)TOK*HIDD];
__device__ float g_tab [4*6*49*64];
__device__ bf16  g_wqkv[(size_t)576*192];
__device__ bf16  g_wprj[(size_t)192*192];
__device__ bf16  g_wfc1[(size_t)HIDD*192];
__device__ bf16  g_wfc2[(size_t)192*HIDD];

// ---------------- PTX helpers ----------------
__device__ __forceinline__ uint32_t smem_u32(const void* p) {
    uint32_t a;
    asm("{ .reg .u64 t; cvta.to.shared.u64 t, %1; cvt.u32.u64 %0, t; }"
        : "=r"(a) : "l"(p));
    return a;
}
__device__ __forceinline__ void cp16(uint32_t s, const void* g) {
    asm volatile("cp.async.cg.shared.global [%0], [%1], 16;" :: "r"(s), "l"(g));
}
#define CP_COMMIT() asm volatile("cp.async.commit_group;" ::: "memory")
__device__ __forceinline__ void ldsm4(uint32_t& r0, uint32_t& r1, uint32_t& r2,
                                      uint32_t& r3, uint32_t a) {
    asm volatile("ldmatrix.sync.aligned.m8n8.x4.shared.b16 {%0,%1,%2,%3}, [%4];"
                 : "=r"(r0), "=r"(r1), "=r"(r2), "=r"(r3) : "r"(a));
}
__device__ __forceinline__ void ldsm4t(uint32_t& r0, uint32_t& r1, uint32_t& r2,
                                       uint32_t& r3, uint32_t a) {
    asm volatile("ldmatrix.sync.aligned.m8n8.x4.trans.shared.b16 {%0,%1,%2,%3}, [%4];"
                 : "=r"(r0), "=r"(r1), "=r"(r2), "=r"(r3) : "r"(a));
}
__device__ __forceinline__ void mma_bf16(float* c, const uint32_t* a, const uint32_t* b) {
    asm volatile(
        "mma.sync.aligned.m16n8k16.row.col.f32.bf16.bf16.f32 "
        "{%0,%1,%2,%3}, {%4,%5,%6,%7}, {%8,%9}, {%0,%1,%2,%3};"
        : "+f"(c[0]), "+f"(c[1]), "+f"(c[2]), "+f"(c[3])
        : "r"(a[0]), "r"(a[1]), "r"(a[2]), "r"(a[3]), "r"(b[0]), "r"(b[1]));
}
__device__ __forceinline__ uint32_t packbf2(float lo, float hi) {
    __nv_bfloat162 h2 = __floats2bfloat162_rn(lo, hi);
    return *reinterpret_cast<uint32_t*>(&h2);
}

// ============ merged prep: 4 weight transposes + bias/mask tables =========
__device__ __forceinline__ void wtrans_tile(const float* W, bf16* Wt,
                                            int K, int N, int bx, int by, int t)
{
    __shared__ float tile[32][33];
    int k0 = by * 32, n0 = bx * 32;
    int tx = t & 31, ty = t >> 5;   // 32 x 8
#pragma unroll
    for (int i = 0; i < 32; i += 8)
        tile[ty + i][tx] = W[(size_t)(k0 + ty + i) * N + n0 + tx];
    __syncthreads();
#pragma unroll
    for (int i = 0; i < 32; i += 8)
        Wt[(size_t)(n0 + ty + i) * K + k0 + tx] = __float2bfloat16(tile[tx][ty + i]);
}

__global__ void prep_kernel(const float* __restrict__ qkv_w,
                            const float* __restrict__ proj_w,
                            const float* __restrict__ fc1_w,
                            const float* __restrict__ fc2_w,
                            const float* __restrict__ rel_bias)
{
    const int b = blockIdx.x;
    const int t = threadIdx.x;
    if (b < 108) {
        wtrans_tile(qkv_w, g_wqkv, CC, 3 * CC, b % 18, b / 18, t);
    } else if (b < 144) {
        int bb = b - 108;
        wtrans_tile(proj_w, g_wprj, CC, CC, bb % 6, bb / 6, t);
    } else if (b < 288) {
        int bb = b - 144;
        wtrans_tile(fc1_w, g_wfc1, CC, HIDD, bb % 24, bb / 24, t);
    } else if (b < 432) {
        int bb = b - 288;
        wtrans_tile(fc2_w, g_wfc2, HIDD, CC, bb % 6, bb / 6, t);
    } else {
        int bh = b - 432;             // 0..23 = mi*6 + h
        int mi = bh / 6, h = bh % 6;
        int eh = mi >> 1, ew = mi & 1;
        for (int idx = t; idx < NN * 64; idx += 256) {
            int i = idx >> 6, j = idx & 63;
            float val;
            if (j >= NN) val = -1e30f;
            else {
                int ih = i / WSZ, iw = i % WSZ, jh = j / WSZ, jw = j % WSZ;
                int dh = ih - jh + (WSZ - 1), dw = iw - jw + (WSZ - 1);
                float bias = rel_bias[(dh * (2 * WSZ - 1) + dw) * NHH + h];
                int ai = eh ? (ih < WSZ - SSZ ? 1 : 2) : 0;
                int bi = ew ? (iw < WSZ - SSZ ? 1 : 2) : 0;
                int aj = eh ? (jh < WSZ - SSZ ? 1 : 2) : 0;
                int bj = ew ? (jw < WSZ - SSZ ? 1 : 2) : 0;
                float mask = ((ai * 3 + bi) != (aj * 3 + bj)) ? -100.0f : 0.0f;
                val = bias + mask;
            }
            g_tab[(size_t)bh * (NN * 64) + idx] = val;
        }
    }
}

// ---------------- LayerNorm (warp per token), float2 loads, bf16 out ------
template<int MODE>
__global__ void ln_kernel(const float* __restrict__ x,
                          const float* __restrict__ gamma,
                          const float* __restrict__ beta)
{
    int warp = (blockIdx.x * blockDim.x + threadIdx.x) >> 5;
    int lane = threadIdx.x & 31;
    if (warp >= TOK) return;

    const float* src;
    bf16* dst;
    if (MODE == 0) {
        int tw = warp;
        int w  = tw / NN, n = tw % NN;
        int bb = w / NWIN, wi = w % NWIN;
        int wrow = wi >> 3, wcol = wi & 7;
        int ih = n / WSZ, iw = n % WSZ;
        int gh = wrow * WSZ + ih + SSZ; if (gh >= HH) gh -= HH;
        int gw = wcol * WSZ + iw + SSZ; if (gw >= WW) gw -= WW;
        src = x + ((size_t)bb * HH * WW + (size_t)gh * WW + gw) * CC;
        dst = g_xw + (size_t)tw * CC;
    } else {
        src = g_y + (size_t)warp * CC;
        dst = g_xm + (size_t)warp * CC;
    }

    float2 v[3];
    float s = 0.f;
#pragma unroll
    for (int k = 0; k < 3; k++) {
        v[k] = *(const float2*)&src[lane * 2 + 64 * k];
        s += v[k].x + v[k].y;
    }
#pragma unroll
    for (int o = 16; o; o >>= 1) s += __shfl_xor_sync(0xffffffffu, s, o);
    float mean = s * (1.0f / CC);
    float vs = 0.f;
#pragma unroll
    for (int k = 0; k < 3; k++) {
        float dx = v[k].x - mean, dy = v[k].y - mean;
        vs += dx * dx + dy * dy;
    }
#pragma unroll
    for (int o = 16; o; o >>= 1) vs += __shfl_xor_sync(0xffffffffu, vs, o);
    float inv = rsqrtf(vs * (1.0f / CC) + 1e-5f);
#pragma unroll
    for (int k = 0; k < 3; k++) {
        int c = lane * 2 + 64 * k;
        float2 g = *(const float2*)&gamma[c];
        float2 bb2 = *(const float2*)&beta[c];
        float o0 = (v[k].x - mean) * inv * g.x + bb2.x;
        float o1 = (v[k].y - mean) * inv * g.y + bb2.y;
        *(__nv_bfloat162*)&dst[c] = __floats2bfloat162_rn(o0, o1);
    }
}

// ================= bf16 mma GEMM (round-13 proven config) =================
// BM=128, BN=64, BK=64. 128 threads = 4 warps (4m x 1n), warp tile 32x64.
// 2-stage cp.async double buffer, dynamic smem (55.3 KB).
#define SRB   144                       // smem row bytes
#define A_STG_B (128 * SRB)             // 18432
#define B_STG_B (64  * SRB)             // 9216
#define G_SMEM  (2 * (A_STG_B + B_STG_B))   // 55296

template<int ACT, int RESM, bool OBF>
__global__ void __launch_bounds__(128)
gemm_bf16(const bf16* __restrict__ A, const bf16* __restrict__ Wt,
          const float* __restrict__ bias, const float* __restrict__ res,
          void* __restrict__ Cv, int M, int N, int K)
{
    extern __shared__ __align__(16) char smem[];
    const uint32_t asB = smem_u32(smem);
    const uint32_t bsB = asB + 2 * A_STG_B;

    const int t    = threadIdx.x;
    const int lane = t & 31;
    const int wid  = t >> 5;
    const int m0   = blockIdx.y << 7;
    const int n0   = blockIdx.x << 6;

    const int T = K >> 6;

    auto load_tiles = [&](int kt, int b) {
        const int k0 = kt << 6;
        uint32_t aD = asB + b * A_STG_B;
#pragma unroll
        for (int r = 0; r < 8; r++) {
            int i = t + 128 * r;
            int row = i >> 3, c = i & 7;
            cp16(aD + row * SRB + (c << 4),
                 A + (size_t)(m0 + row) * K + k0 + (c << 3));
        }
        uint32_t bD = bsB + b * B_STG_B;
#pragma unroll
        for (int r = 0; r < 4; r++) {
            int i = t + 128 * r;
            int row = i >> 3, c = i & 7;
            cp16(bD + row * SRB + (c << 4),
                 Wt + (size_t)(n0 + row) * K + k0 + (c << 3));
        }
        CP_COMMIT();
    };

    float acc[2][8][4];
#pragma unroll
    for (int i = 0; i < 2; i++)
#pragma unroll
        for (int j = 0; j < 8; j++)
#pragma unroll
            for (int q = 0; q < 4; q++) acc[i][j][q] = 0.f;

    const uint32_t aFrag = (wid * 32 + (lane & 15)) * SRB + ((lane >> 4) << 4);
    const uint32_t bFrag = ((lane & 7) + (((lane >> 4) & 1) << 3)) * SRB
                           + (((lane >> 3) & 1) << 4);

    load_tiles(0, 0);

    for (int kt = 0; kt < T; kt++) {
        const int b = kt & 1;
        if (kt + 1 < T) {
            load_tiles(kt + 1, b ^ 1);
            asm volatile("cp.async.wait_group 1;" ::: "memory");
        } else {
            asm volatile("cp.async.wait_group 0;" ::: "memory");
        }
        __syncthreads();

        const uint32_t aB = asB + b * A_STG_B + aFrag;
        const uint32_t bB = bsB + b * B_STG_B + bFrag;
#pragma unroll
        for (int kk = 0; kk < 4; kk++) {
            uint32_t av[2][4], bv[8][2];
            ldsm4(av[0][0], av[0][1], av[0][2], av[0][3], aB + kk * 32);
            ldsm4(av[1][0], av[1][1], av[1][2], av[1][3], aB + 16 * SRB + kk * 32);
#pragma unroll
            for (int g = 0; g < 4; g++)
                ldsm4(bv[2 * g][0], bv[2 * g][1], bv[2 * g + 1][0], bv[2 * g + 1][1],
                      bB + g * 16 * SRB + kk * 32);
#pragma unroll
            for (int mt = 0; mt < 2; mt++)
#pragma unroll
                for (int nt = 0; nt < 8; nt++)
                    mma_bf16(acc[mt][nt], av[mt], bv[nt]);
        }
        __syncthreads();
    }

    // ---------------- epilogue ----------------
    const int colBase = n0 + ((lane & 3) << 1);
    const int rowBase = m0 + wid * 32 + (lane >> 2);
#pragma unroll
    for (int mt = 0; mt < 2; mt++) {
#pragma unroll
        for (int half = 0; half < 2; half++) {
            const int r = rowBase + mt * 16 + half * 8;
            size_t outRow = (size_t)r;
            if (RESM == 2) {
                int wq = r / NN, nq = r % NN;
                int bq = wq >> 6, wiq = wq & 63;
                int gh = (wiq >> 3) * WSZ + nq / WSZ + SSZ; if (gh >= HH) gh -= HH;
                int gw = (wiq & 7)  * WSZ + nq % WSZ + SSZ; if (gw >= WW) gw -= WW;
                outRow = (size_t)bq * (HH * WW) + gh * WW + gw;
            }
            const float* Rrow = res + outRow * N;
#pragma unroll
            for (int nt = 0; nt < 8; nt++) {
                const int c0 = colBase + nt * 8;
                float v0 = acc[mt][nt][half * 2 + 0] + bias[c0];
                float v1 = acc[mt][nt][half * 2 + 1] + bias[c0 + 1];
                if (ACT == 1) {
                    v0 = 0.5f * v0 * (1.0f + erff(v0 * 0.70710678118654752f));
                    v1 = 0.5f * v1 * (1.0f + erff(v1 * 0.70710678118654752f));
                }
                if (RESM != 0) { v0 += Rrow[c0]; v1 += Rrow[c0 + 1]; }
                if (OBF) {
                    bf16* Crow = (bf16*)Cv + outRow * N;
                    *(__nv_bfloat162*)&Crow[c0] = __floats2bfloat162_rn(v0, v1);
                } else {
                    float* Crow = (float*)Cv + outRow * N;
                    float2 o; o.x = v0; o.y = v1;
                    *(float2*)&Crow[c0] = o;
                }
            }
        }
    }
}

// ================= tensor-core windowed attention: 2 heads / block ========
// Round-13 structure + split QK/V commit groups so S-compute overlaps V load.
#define SROW 40
#define ATT_STG (64 * SROW)

__global__ void __launch_bounds__(256)
attn_mma_kernel()
{
    __shared__ __align__(16) bf16 Qs[2][ATT_STG];
    __shared__ __align__(16) bf16 Ks[2][ATT_STG];
    __shared__ __align__(16) bf16 Vs[2][ATT_STG];

    const int blk = blockIdx.x;
    const int w = blk / 3, hp = blk % 3;
    const int t = threadIdx.x;
    const int lane = t & 31;
    const int wid = t >> 5;
    const int hs  = wid >> 2;
    const int mt  = wid & 3;
    const int h   = hp * 2 + hs;

    const uint32_t qB = smem_u32(Qs) + hs * (ATT_STG * 2);
    const uint32_t kB = smem_u32(Ks) + hs * (ATT_STG * 2);
    const uint32_t vB = smem_u32(Vs) + hs * (ATT_STG * 2);

    for (int i = t; i < 2 * 15 * 20; i += 256) {
        int hsel = i / 300, j = i % 300;
        int off = hsel * (ATT_STG / 2) + (49 + j / 20) * 20 + (j % 20);
        ((uint32_t*)Qs)[off] = 0;
        ((uint32_t*)Ks)[off] = 0;
        ((uint32_t*)Vs)[off] = 0;
    }

    const bf16* base = g_qkv + (size_t)w * NN * (3 * CC) + hp * 2 * HD;
    // group 0: Q + K
    for (int i = t; i < 2 * NN * 4; i += 256) {
        int hsel = i / (NN * 4), j = i % (NN * 4);
        int r = j >> 2, c = (j & 3) << 3;
        const bf16* src = base + (size_t)r * (3 * CC) + hsel * HD + c;
        uint32_t d = hsel * (ATT_STG * 2) + r * 80 + (c << 1);
        cp16(smem_u32(Qs) + d, src);
        cp16(smem_u32(Ks) + d, src + CC);
    }
    CP_COMMIT();
    // group 1: V
    for (int i = t; i < 2 * NN * 4; i += 256) {
        int hsel = i / (NN * 4), j = i % (NN * 4);
        int r = j >> 2, c = (j & 3) << 3;
        const bf16* src = base + (size_t)r * (3 * CC) + hsel * HD + c;
        uint32_t d = hsel * (ATT_STG * 2) + r * 80 + (c << 1);
        cp16(smem_u32(Vs) + d, src + 2 * CC);
    }
    CP_COMMIT();

    asm volatile("cp.async.wait_group 1;" ::: "memory");   // Q,K ready
    __syncthreads();

    // ---- S = Q K^T ----
    float sacc[8][4];
#pragma unroll
    for (int i = 0; i < 8; i++)
#pragma unroll
        for (int q = 0; q < 4; q++) sacc[i][q] = 0.f;

    const uint32_t aAddr = qB + (mt * 16 + (lane & 15)) * 80 + ((lane >> 4) << 4);
    const uint32_t bAddr = kB + ((lane & 7) + (((lane >> 4) & 1) << 3)) * 80
                              + (((lane >> 3) & 1) << 4);
#pragma unroll
    for (int kk = 0; kk < 2; kk++) {
        uint32_t av[4];
        ldsm4(av[0], av[1], av[2], av[3], aAddr + kk * 32);
#pragma unroll
        for (int ng = 0; ng < 4; ng++) {
            uint32_t b0, b1, b2, b3;
            ldsm4(b0, b1, b2, b3, bAddr + ng * 16 * 80 + kk * 32);
            uint32_t bv0[2] = {b0, b1}, bv1[2] = {b2, b3};
            mma_bf16(sacc[2 * ng],     av, bv0);
            mma_bf16(sacc[2 * ng + 1], av, bv1);
        }
    }

    // ---- scale + table + softmax in fragments (V still loading) ----
    const int wi = w & (NWIN - 1);
    const int mi = (((wi >> 3) == 7) ? 2 : 0) + (((wi & 7) == 7) ? 1 : 0);
    const float* tb = g_tab + (size_t)(mi * NHH + h) * (NN * 64);
    const int r0 = mt * 16 + (lane >> 2);
    const float scale = 0.17677669529663687f;

#pragma unroll
    for (int nt = 0; nt < 8; nt++) {
        const int c = nt * 8 + ((lane & 3) << 1);
        float t00 = 0.f, t01 = 0.f, t10 = 0.f, t11 = 0.f;
        if (r0 < NN)     { float2 tt = *(const float2*)&tb[r0 * 64 + c];      t00 = tt.x; t01 = tt.y; }
        if (r0 + 8 < NN) { float2 tt = *(const float2*)&tb[(r0 + 8) * 64 + c]; t10 = tt.x; t11 = tt.y; }
        sacc[nt][0] = sacc[nt][0] * scale + t00;
        sacc[nt][1] = sacc[nt][1] * scale + t01;
        sacc[nt][2] = sacc[nt][2] * scale + t10;
        sacc[nt][3] = sacc[nt][3] * scale + t11;
    }

    float m0 = -1e30f, m1 = -1e30f;
#pragma unroll
    for (int nt = 0; nt < 8; nt++) {
        m0 = fmaxf(m0, fmaxf(sacc[nt][0], sacc[nt][1]));
        m1 = fmaxf(m1, fmaxf(sacc[nt][2], sacc[nt][3]));
    }
    m0 = fmaxf(m0, __shfl_xor_sync(0xffffffffu, m0, 1));
    m0 = fmaxf(m0, __shfl_xor_sync(0xffffffffu, m0, 2));
    m1 = fmaxf(m1, __shfl_xor_sync(0xffffffffu, m1, 1));
    m1 = fmaxf(m1, __shfl_xor_sync(0xffffffffu, m1, 2));

    float s0 = 0.f, s1 = 0.f;
#pragma unroll
    for (int nt = 0; nt < 8; nt++) {
        sacc[nt][0] = __expf(sacc[nt][0] - m0);
        sacc[nt][1] = __expf(sacc[nt][1] - m0);
        sacc[nt][2] = __expf(sacc[nt][2] - m1);
        sacc[nt][3] = __expf(sacc[nt][3] - m1);
        s0 += sacc[nt][0] + sacc[nt][1];
        s1 += sacc[nt][2] + sacc[nt][3];
    }
    s0 += __shfl_xor_sync(0xffffffffu, s0, 1);
    s0 += __shfl_xor_sync(0xffffffffu, s0, 2);
    s1 += __shfl_xor_sync(0xffffffffu, s1, 1);
    s1 += __shfl_xor_sync(0xffffffffu, s1, 2);
    const float i0 = 1.0f / s0, i1 = 1.0f / s1;

    asm volatile("cp.async.wait_group 0;" ::: "memory");   // V ready
    __syncthreads();

    // ---- O = P V ----
    float oacc[4][4];
#pragma unroll
    for (int i = 0; i < 4; i++)
#pragma unroll
        for (int q = 0; q < 4; q++) oacc[i][q] = 0.f;

    const uint32_t vAddr = vB + ((((lane >> 3) & 1) << 3) + (lane & 7)) * 80
                              + (((lane >> 4) & 1) << 4);
#pragma unroll
    for (int kk = 0; kk < 4; kk++) {
        uint32_t pa[4];
        pa[0] = packbf2(sacc[2 * kk][0] * i0,     sacc[2 * kk][1] * i0);
        pa[1] = packbf2(sacc[2 * kk][2] * i1,     sacc[2 * kk][3] * i1);
        pa[2] = packbf2(sacc[2 * kk + 1][0] * i0, sacc[2 * kk + 1][1] * i0);
        pa[3] = packbf2(sacc[2 * kk + 1][2] * i1, sacc[2 * kk + 1][3] * i1);
        uint32_t b0, b1, b2, b3;
        ldsm4t(b0, b1, b2, b3, vAddr + kk * 16 * 80);
        { uint32_t bv0[2] = {b0, b1}, bv1[2] = {b2, b3};
          mma_bf16(oacc[0], pa, bv0); mma_bf16(oacc[1], pa, bv1); }
        ldsm4t(b0, b1, b2, b3, vAddr + kk * 16 * 80 + 32);
        { uint32_t bv0[2] = {b0, b1}, bv1[2] = {b2, b3};
          mma_bf16(oacc[2], pa, bv0); mma_bf16(oacc[3], pa, bv1); }
    }

    bf16* outB = g_attn + (size_t)w * NN * CC + h * HD;
#pragma unroll
    for (int nt = 0; nt < 4; nt++) {
        const int c = nt * 8 + ((lane & 3) << 1);
        if (r0 < NN)
            *(__nv_bfloat162*)&outB[(size_t)r0 * CC + c] =
                __floats2bfloat162_rn(oacc[nt][0], oacc[nt][1]);
        if (r0 + 8 < NN)
            *(__nv_bfloat162*)&outB[(size_t)(r0 + 8) * CC + c] =
                __floats2bfloat162_rn(oacc[nt][2], oacc[nt][3]);
    }
}

// ---------------- launch ----------------
extern "C" void kernel_launch(void* const* d_in, const int* in_sizes, int n_in,
                              void* d_out, int out_size)
{
    const float* x       = (const float*)d_in[0];
    const float* norm1_g = (const float*)d_in[1];
    const float* norm1_b = (const float*)d_in[2];
    const float* qkv_w   = (const float*)d_in[3];
    const float* qkv_b   = (const float*)d_in[4];
    const float* rel_b   = (const float*)d_in[5];
    const float* proj_w  = (const float*)d_in[6];
    const float* proj_b  = (const float*)d_in[7];
    const float* norm2_g = (const float*)d_in[8];
    const float* norm2_b = (const float*)d_in[9];
    const float* fc1_w   = (const float*)d_in[10];
    const float* fc1_b   = (const float*)d_in[11];
    const float* fc2_w   = (const float*)d_in[12];
    const float* fc2_b   = (const float*)d_in[13];
    float* out = (float*)d_out;

    bf16 *p_xw, *p_qkv, *p_attn, *p_xm, *p_h, *p_wqkv, *p_wprj, *p_wfc1, *p_wfc2;
    float *p_y;
    cudaGetSymbolAddress((void**)&p_xw,   g_xw);
    cudaGetSymbolAddress((void**)&p_qkv,  g_qkv);
    cudaGetSymbolAddress((void**)&p_attn, g_attn);
    cudaGetSymbolAddress((void**)&p_y,    g_y);
    cudaGetSymbolAddress((void**)&p_xm,   g_xm);
    cudaGetSymbolAddress((void**)&p_h,    g_h);
    cudaGetSymbolAddress((void**)&p_wqkv, g_wqkv);
    cudaGetSymbolAddress((void**)&p_wprj, g_wprj);
    cudaGetSymbolAddress((void**)&p_wfc1, g_wfc1);
    cudaGetSymbolAddress((void**)&p_wfc2, g_wfc2);

    cudaFuncSetAttribute(gemm_bf16<0, 0, true>,  cudaFuncAttributeMaxDynamicSharedMemorySize, G_SMEM);
    cudaFuncSetAttribute(gemm_bf16<0, 2, false>, cudaFuncAttributeMaxDynamicSharedMemorySize, G_SMEM);
    cudaFuncSetAttribute(gemm_bf16<1, 0, true>,  cudaFuncAttributeMaxDynamicSharedMemorySize, G_SMEM);
    cudaFuncSetAttribute(gemm_bf16<0, 1, false>, cudaFuncAttributeMaxDynamicSharedMemorySize, G_SMEM);

    const int lnBlocks = TOK / 8;

    // 0) merged prep
    prep_kernel<<<456, 256>>>(qkv_w, proj_w, fc1_w, fc2_w, rel_b);

    // 1) LN1 + shift + window partition (bf16)
    ln_kernel<0><<<lnBlocks, 256>>>(x, norm1_g, norm1_b);

    // 2) QKV gemm [TOK,192]x[192,576] -> bf16
    gemm_bf16<0, 0, true><<<dim3(576 / 64, TOK / 128), 128, G_SMEM>>>(
        p_xw, p_wqkv, qkv_b, nullptr, p_qkv, TOK, 3 * CC, CC);

    // 3) tensor-core windowed attention (2 heads / block)
    attn_mma_kernel<<<(TOK / NN) * 3, 256>>>();

    // 4) proj gemm + window-reverse/unshift scatter + residual -> g_y (fp32)
    gemm_bf16<0, 2, false><<<dim3(192 / 64, TOK / 128), 128, G_SMEM>>>(
        p_attn, p_wprj, proj_b, x, p_y, TOK, CC, CC);

    // 5) LN2 (bf16)
    ln_kernel<1><<<lnBlocks, 256>>>(nullptr, norm2_g, norm2_b);

    // 6) fc1 + exact GELU [TOK,192]x[192,768] -> bf16
    gemm_bf16<1, 0, true><<<dim3(HIDD / 64, TOK / 128), 128, G_SMEM>>>(
        p_xm, p_wfc1, fc1_b, nullptr, p_h, TOK, HIDD, CC);

    // 7) fc2 + residual [TOK,768]x[768,192] -> d_out (fp32)
    gemm_bf16<0, 1, false><<<dim3(192 / 64, TOK / 128), 128, G_SMEM>>>(
        p_h, p_wfc2, fc2_b, p_y, out, TOK, CC, HIDD);
}

// round 16
// speedup vs baseline: 1.0542x; 1.0243x over previous
#include <cuda_runtime.h>
#include <cuda_bf16.h>
#include <math.h>
#include <stdint.h>

// ---------------- problem constants ----------------
#define BNUM 32
#define HH   56
#define WW   56
#define CC   192
#define NHH  6
#define HD   32
#define WSZ  7
#define SSZ  3
#define NN   49
#define NWIN 64
#define TOK  (BNUM*HH*WW)   // 100352
#define HIDD 768

typedef __nv_bfloat16 bf16;

// ---------------- scratch ----------------
__device__ bf16  g_xw  [(size_t)TOK*CC];
__device__ bf16  g_qkv [(size_t)TOK*3*CC];
__device__ bf16  g_attn[(size_t)TOK*CC];
__device__ float g_y   [(size_t)TOK*CC];
__device__ bf16  g_xm  [(size_t)TOK*CC];
__device__ bf16  g_h   [(size_t)TOK*HIDD];
__device__ float g_tab [4*6*49*64];
__device__ bf16  g_wqkv[(size_t)576*192];
__device__ bf16  g_wprj[(size_t)192*192];
__device__ bf16  g_wfc1[(size_t)HIDD*192];
__device__ bf16  g_wfc2[(size_t)192*HIDD];

// ---------------- PTX helpers ----------------
__device__ __forceinline__ uint32_t smem_u32(const void* p) {
    uint32_t a;
    asm("{ .reg .u64 t; cvta.to.shared.u64 t, %1; cvt.u32.u64 %0, t; }"
        : "=r"(a) : "l"(p));
    return a;
}
__device__ __forceinline__ void cp16(uint32_t s, const void* g) {
    asm volatile("cp.async.cg.shared.global [%0], [%1], 16;" :: "r"(s), "l"(g));
}
#define CP_COMMIT() asm volatile("cp.async.commit_group;" ::: "memory")
__device__ __forceinline__ void ldsm4(uint32_t& r0, uint32_t& r1, uint32_t& r2,
                                      uint32_t& r3, uint32_t a) {
    asm volatile("ldmatrix.sync.aligned.m8n8.x4.shared.b16 {%0,%1,%2,%3}, [%4];"
                 : "=r"(r0), "=r"(r1), "=r"(r2), "=r"(r3) : "r"(a));
}
__device__ __forceinline__ void ldsm4t(uint32_t& r0, uint32_t& r1, uint32_t& r2,
                                       uint32_t& r3, uint32_t a) {
    asm volatile("ldmatrix.sync.aligned.m8n8.x4.trans.shared.b16 {%0,%1,%2,%3}, [%4];"
                 : "=r"(r0), "=r"(r1), "=r"(r2), "=r"(r3) : "r"(a));
}
__device__ __forceinline__ void mma_bf16(float* c, const uint32_t* a, const uint32_t* b) {
    asm volatile(
        "mma.sync.aligned.m16n8k16.row.col.f32.bf16.bf16.f32 "
        "{%0,%1,%2,%3}, {%4,%5,%6,%7}, {%8,%9}, {%0,%1,%2,%3};"
        : "+f"(c[0]), "+f"(c[1]), "+f"(c[2]), "+f"(c[3])
        : "r"(a[0]), "r"(a[1]), "r"(a[2]), "r"(a[3]), "r"(b[0]), "r"(b[1]));
}
__device__ __forceinline__ uint32_t packbf2(float lo, float hi) {
    __nv_bfloat162 h2 = __floats2bfloat162_rn(lo, hi);
    return *reinterpret_cast<uint32_t*>(&h2);
}

// ---------------- LayerNorm body (warp per token) --------------------------
__device__ __forceinline__ void ln_token(const float* __restrict__ src,
                                         bf16* __restrict__ dst,
                                         const float* __restrict__ gamma,
                                         const float* __restrict__ beta,
                                         int lane)
{
    float2 v[3];
    float s = 0.f;
#pragma unroll
    for (int k = 0; k < 3; k++) {
        v[k] = *(const float2*)&src[lane * 2 + 64 * k];
        s += v[k].x + v[k].y;
    }
#pragma unroll
    for (int o = 16; o; o >>= 1) s += __shfl_xor_sync(0xffffffffu, s, o);
    float mean = s * (1.0f / CC);
    float vs = 0.f;
#pragma unroll
    for (int k = 0; k < 3; k++) {
        float dx = v[k].x - mean, dy = v[k].y - mean;
        vs += dx * dx + dy * dy;
    }
#pragma unroll
    for (int o = 16; o; o >>= 1) vs += __shfl_xor_sync(0xffffffffu, vs, o);
    float inv = rsqrtf(vs * (1.0f / CC) + 1e-5f);
#pragma unroll
    for (int k = 0; k < 3; k++) {
        int c = lane * 2 + 64 * k;
        float2 g = *(const float2*)&gamma[c];
        float2 bb2 = *(const float2*)&beta[c];
        float o0 = (v[k].x - mean) * inv * g.x + bb2.x;
        float o1 = (v[k].y - mean) * inv * g.y + bb2.y;
        *(__nv_bfloat162*)&dst[c] = __floats2bfloat162_rn(o0, o1);
    }
}

// ============ merged prep: weight transposes + tables + LN1 ===============
// blocks 0..107   wqkv, 108..143 wprj, 144..287 wfc1, 288..431 wfc2,
// blocks 432..455 tab, blocks 456.. LN1 (8 tokens per block).
__device__ __forceinline__ void wtrans_tile(const float* W, bf16* Wt,
                                            int K, int N, int bx, int by, int t)
{
    __shared__ float tile[32][33];
    int k0 = by * 32, n0 = bx * 32;
    int tx = t & 31, ty = t >> 5;
#pragma unroll
    for (int i = 0; i < 32; i += 8)
        tile[ty + i][tx] = W[(size_t)(k0 + ty + i) * N + n0 + tx];
    __syncthreads();
#pragma unroll
    for (int i = 0; i < 32; i += 8)
        Wt[(size_t)(n0 + ty + i) * K + k0 + tx] = __float2bfloat16(tile[tx][ty + i]);
}

__global__ void prep_kernel(const float* __restrict__ qkv_w,
                            const float* __restrict__ proj_w,
                            const float* __restrict__ fc1_w,
                            const float* __restrict__ fc2_w,
                            const float* __restrict__ rel_bias,
                            const float* __restrict__ x,
                            const float* __restrict__ norm1_g,
                            const float* __restrict__ norm1_b)
{
    const int b = blockIdx.x;
    const int t = threadIdx.x;
    if (b < 108) {
        wtrans_tile(qkv_w, g_wqkv, CC, 3 * CC, b % 18, b / 18, t);
    } else if (b < 144) {
        int bb = b - 108;
        wtrans_tile(proj_w, g_wprj, CC, CC, bb % 6, bb / 6, t);
    } else if (b < 288) {
        int bb = b - 144;
        wtrans_tile(fc1_w, g_wfc1, CC, HIDD, bb % 24, bb / 24, t);
    } else if (b < 432) {
        int bb = b - 288;
        wtrans_tile(fc2_w, g_wfc2, HIDD, CC, bb % 6, bb / 6, t);
    } else if (b < 456) {
        int bh = b - 432;
        int mi = bh / 6, h = bh % 6;
        int eh = mi >> 1, ew = mi & 1;
        for (int idx = t; idx < NN * 64; idx += 256) {
            int i = idx >> 6, j = idx & 63;
            float val;
            if (j >= NN) val = -1e30f;
            else {
                int ih = i / WSZ, iw = i % WSZ, jh = j / WSZ, jw = j % WSZ;
                int dh = ih - jh + (WSZ - 1), dw = iw - jw + (WSZ - 1);
                float bias = rel_bias[(dh * (2 * WSZ - 1) + dw) * NHH + h];
                int ai = eh ? (ih < WSZ - SSZ ? 1 : 2) : 0;
                int bi = ew ? (iw < WSZ - SSZ ? 1 : 2) : 0;
                int aj = eh ? (jh < WSZ - SSZ ? 1 : 2) : 0;
                int bj = ew ? (jw < WSZ - SSZ ? 1 : 2) : 0;
                float mask = ((ai * 3 + bi) != (aj * 3 + bj)) ? -100.0f : 0.0f;
                val = bias + mask;
            }
            g_tab[(size_t)bh * (NN * 64) + idx] = val;
        }
    } else {
        // LN1 + shift + window partition
        int warp = (b - 456) * 8 + (t >> 5);
        int lane = t & 31;
        if (warp < TOK) {
            int w  = warp / NN, n = warp % NN;
            int bb = w / NWIN, wi = w % NWIN;
            int wrow = wi >> 3, wcol = wi & 7;
            int ih = n / WSZ, iw = n % WSZ;
            int gh = wrow * WSZ + ih + SSZ; if (gh >= HH) gh -= HH;
            int gw = wcol * WSZ + iw + SSZ; if (gw >= WW) gw -= WW;
            const float* src = x + ((size_t)bb * HH * WW + (size_t)gh * WW + gw) * CC;
            bf16* dst = g_xw + (size_t)warp * CC;
            ln_token(src, dst, norm1_g, norm1_b, lane);
        }
    }
}

// ---------------- LN2 (warp per token) ------------------------------------
__global__ void ln2_kernel(const float* __restrict__ gamma,
                           const float* __restrict__ beta)
{
    int warp = (blockIdx.x * blockDim.x + threadIdx.x) >> 5;
    int lane = threadIdx.x & 31;
    if (warp >= TOK) return;
    ln_token(g_y + (size_t)warp * CC, g_xm + (size_t)warp * CC, gamma, beta, lane);
}

// ================= bf16 mma GEMM (round-13 proven config) =================
// BM=128, BN=64, BK=64. 128 threads = 4 warps (4m x 1n), warp tile 32x64.
#define SRB   144
#define A_STG_B (128 * SRB)
#define B_STG_B (64  * SRB)
#define G_SMEM  (2 * (A_STG_B + B_STG_B))   // 55296

template<int ACT, int RESM, bool OBF>
__global__ void __launch_bounds__(128)
gemm_bf16(const bf16* __restrict__ A, const bf16* __restrict__ Wt,
          const float* __restrict__ bias, const float* __restrict__ res,
          void* __restrict__ Cv, int M, int N, int K)
{
    extern __shared__ __align__(16) char smem[];
    const uint32_t asB = smem_u32(smem);
    const uint32_t bsB = asB + 2 * A_STG_B;

    const int t    = threadIdx.x;
    const int lane = t & 31;
    const int wid  = t >> 5;
    const int m0   = blockIdx.y << 7;
    const int n0   = blockIdx.x << 6;

    const int T = K >> 6;

    auto load_tiles = [&](int kt, int b) {
        const int k0 = kt << 6;
        uint32_t aD = asB + b * A_STG_B;
#pragma unroll
        for (int r = 0; r < 8; r++) {
            int i = t + 128 * r;
            int row = i >> 3, c = i & 7;
            cp16(aD + row * SRB + (c << 4),
                 A + (size_t)(m0 + row) * K + k0 + (c << 3));
        }
        uint32_t bD = bsB + b * B_STG_B;
#pragma unroll
        for (int r = 0; r < 4; r++) {
            int i = t + 128 * r;
            int row = i >> 3, c = i & 7;
            cp16(bD + row * SRB + (c << 4),
                 Wt + (size_t)(n0 + row) * K + k0 + (c << 3));
        }
        CP_COMMIT();
    };

    float acc[2][8][4];
#pragma unroll
    for (int i = 0; i < 2; i++)
#pragma unroll
        for (int j = 0; j < 8; j++)
#pragma unroll
            for (int q = 0; q < 4; q++) acc[i][j][q] = 0.f;

    const uint32_t aFrag = (wid * 32 + (lane & 15)) * SRB + ((lane >> 4) << 4);
    const uint32_t bFrag = ((lane & 7) + (((lane >> 4) & 1) << 3)) * SRB
                           + (((lane >> 3) & 1) << 4);

    load_tiles(0, 0);

    for (int kt = 0; kt < T; kt++) {
        const int b = kt & 1;
        if (kt + 1 < T) {
            load_tiles(kt + 1, b ^ 1);
            asm volatile("cp.async.wait_group 1;" ::: "memory");
        } else {
            asm volatile("cp.async.wait_group 0;" ::: "memory");
        }
        __syncthreads();

        const uint32_t aB = asB + b * A_STG_B + aFrag;
        const uint32_t bB = bsB + b * B_STG_B + bFrag;
#pragma unroll
        for (int kk = 0; kk < 4; kk++) {
            uint32_t av[2][4], bv[8][2];
            ldsm4(av[0][0], av[0][1], av[0][2], av[0][3], aB + kk * 32);
            ldsm4(av[1][0], av[1][1], av[1][2], av[1][3], aB + 16 * SRB + kk * 32);
#pragma unroll
            for (int g = 0; g < 4; g++)
                ldsm4(bv[2 * g][0], bv[2 * g][1], bv[2 * g + 1][0], bv[2 * g + 1][1],
                      bB + g * 16 * SRB + kk * 32);
#pragma unroll
            for (int mt = 0; mt < 2; mt++)
#pragma unroll
                for (int nt = 0; nt < 8; nt++)
                    mma_bf16(acc[mt][nt], av[mt], bv[nt]);
        }
        __syncthreads();
    }

    // ---------------- epilogue ----------------
    const int colBase = n0 + ((lane & 3) << 1);
    const int rowBase = m0 + wid * 32 + (lane >> 2);
#pragma unroll
    for (int mt = 0; mt < 2; mt++) {
#pragma unroll
        for (int half = 0; half < 2; half++) {
            const int r = rowBase + mt * 16 + half * 8;
            size_t outRow = (size_t)r;
            if (RESM == 2) {
                int wq = r / NN, nq = r % NN;
                int bq = wq >> 6, wiq = wq & 63;
                int gh = (wiq >> 3) * WSZ + nq / WSZ + SSZ; if (gh >= HH) gh -= HH;
                int gw = (wiq & 7)  * WSZ + nq % WSZ + SSZ; if (gw >= WW) gw -= WW;
                outRow = (size_t)bq * (HH * WW) + gh * WW + gw;
            }
            const float* Rrow = res + outRow * N;
#pragma unroll
            for (int nt = 0; nt < 8; nt++) {
                const int c0 = colBase + nt * 8;
                float v0 = acc[mt][nt][half * 2 + 0] + bias[c0];
                float v1 = acc[mt][nt][half * 2 + 1] + bias[c0 + 1];
                if (ACT == 1) {
                    v0 = 0.5f * v0 * (1.0f + erff(v0 * 0.70710678118654752f));
                    v1 = 0.5f * v1 * (1.0f + erff(v1 * 0.70710678118654752f));
                }
                if (RESM != 0) { v0 += Rrow[c0]; v1 += Rrow[c0 + 1]; }
                if (OBF) {
                    bf16* Crow = (bf16*)Cv + outRow * N;
                    *(__nv_bfloat162*)&Crow[c0] = __floats2bfloat162_rn(v0, v1);
                } else {
                    float* Crow = (float*)Cv + outRow * N;
                    float2 o; o.x = v0; o.y = v1;
                    *(float2*)&Crow[c0] = o;
                }
            }
        }
    }
}

// ================= tensor-core windowed attention: 2 heads / block ========
// Direct thread->(row,chunk) mapping: no div/mod in load path.
#define SROW 40
#define ATT_STG (64 * SROW)      // bf16 elems per head tile (5120 B)

__global__ void __launch_bounds__(256)
attn_mma_kernel()
{
    __shared__ __align__(16) bf16 Qs[2][ATT_STG];
    __shared__ __align__(16) bf16 Ks[2][ATT_STG];
    __shared__ __align__(16) bf16 Vs[2][ATT_STG];

    const int blk = blockIdx.x;
    const int w = blk / 3, hp = blk % 3;
    const int t = threadIdx.x;
    const int lane = t & 31;
    const int wid = t >> 5;
    const int hs  = wid >> 2;
    const int mt  = wid & 3;
    const int h   = hp * 2 + hs;

    const uint32_t qS = smem_u32(Qs);
    const uint32_t kS = smem_u32(Ks);
    const uint32_t vS = smem_u32(Vs);
    const uint32_t qB = qS + hs * (ATT_STG * 2);
    const uint32_t kB = kS + hs * (ATT_STG * 2);
    const uint32_t vB = vS + hs * (ATT_STG * 2);

    // thread -> (row, chunk): 64 rows x 4 chunks of 16B = 256 threads exactly
    const int rr = t >> 2;                   // 0..63
    const int cb = (t & 3) << 4;             // chunk byte offset 0/16/32/48
    const uint32_t d0 = rr * 80 + cb;        // head 0 tile offset
    const uint32_t d1 = (ATT_STG * 2) + d0;  // head 1 tile offset

    const bf16* base = g_qkv + (size_t)w * NN * (3 * CC) + hp * 2 * HD;
    if (rr < NN) {
        const bf16* s = base + (size_t)rr * (3 * CC) + (cb >> 1);
        // group 0: Q + K (both heads)
        cp16(qS + d0, s);
        cp16(kS + d0, s + CC);
        cp16(qS + d1, s + HD);
        cp16(kS + d1, s + CC + HD);
    } else {
        const uint4 z = {0u, 0u, 0u, 0u};
        *(uint4*)((char*)Qs + d0) = z;  *(uint4*)((char*)Qs + d1) = z;
        *(uint4*)((char*)Ks + d0) = z;  *(uint4*)((char*)Ks + d1) = z;
        *(uint4*)((char*)Vs + d0) = z;  *(uint4*)((char*)Vs + d1) = z;
    }
    CP_COMMIT();
    if (rr < NN) {
        const bf16* s = base + (size_t)rr * (3 * CC) + (cb >> 1);
        // group 1: V (both heads)
        cp16(vS + d0, s + 2 * CC);
        cp16(vS + d1, s + 2 * CC + HD);
    }
    CP_COMMIT();

    asm volatile("cp.async.wait_group 1;" ::: "memory");   // Q,K ready
    __syncthreads();

    // ---- S = Q K^T ----
    float sacc[8][4];
#pragma unroll
    for (int i = 0; i < 8; i++)
#pragma unroll
        for (int q = 0; q < 4; q++) sacc[i][q] = 0.f;

    const uint32_t aAddr = qB + (mt * 16 + (lane & 15)) * 80 + ((lane >> 4) << 4);
    const uint32_t bAddr = kB + ((lane & 7) + (((lane >> 4) & 1) << 3)) * 80
                              + (((lane >> 3) & 1) << 4);
#pragma unroll
    for (int kk = 0; kk < 2; kk++) {
        uint32_t av[4];
        ldsm4(av[0], av[1], av[2], av[3], aAddr + kk * 32);
#pragma unroll
        for (int ng = 0; ng < 4; ng++) {
            uint32_t b0, b1, b2, b3;
            ldsm4(b0, b1, b2, b3, bAddr + ng * 16 * 80 + kk * 32);
            uint32_t bv0[2] = {b0, b1}, bv1[2] = {b2, b3};
            mma_bf16(sacc[2 * ng],     av, bv0);
            mma_bf16(sacc[2 * ng + 1], av, bv1);
        }
    }

    // ---- scale + table + softmax in fragments ----
    const int wi = w & (NWIN - 1);
    const int mi = (((wi >> 3) == 7) ? 2 : 0) + (((wi & 7) == 7) ? 1 : 0);
    const float* tb = g_tab + (size_t)(mi * NHH + h) * (NN * 64);
    const int r0 = mt * 16 + (lane >> 2);
    const bool v0ok = r0 < NN, v1ok = r0 + 8 < NN;
    const int rc0 = v0ok ? r0 : NN - 1;
    const int rc1 = v1ok ? r0 + 8 : NN - 1;
    const float scale = 0.17677669529663687f;

#pragma unroll
    for (int nt = 0; nt < 8; nt++) {
        const int c = nt * 8 + ((lane & 3) << 1);
        float2 ta = *(const float2*)&tb[rc0 * 64 + c];
        float2 tbv = *(const float2*)&tb[rc1 * 64 + c];
        sacc[nt][0] = sacc[nt][0] * scale + (v0ok ? ta.x : 0.f);
        sacc[nt][1] = sacc[nt][1] * scale + (v0ok ? ta.y : 0.f);
        sacc[nt][2] = sacc[nt][2] * scale + (v1ok ? tbv.x : 0.f);
        sacc[nt][3] = sacc[nt][3] * scale + (v1ok ? tbv.y : 0.f);
    }

    float m0 = -1e30f, m1 = -1e30f;
#pragma unroll
    for (int nt = 0; nt < 8; nt++) {
        m0 = fmaxf(m0, fmaxf(sacc[nt][0], sacc[nt][1]));
        m1 = fmaxf(m1, fmaxf(sacc[nt][2], sacc[nt][3]));
    }
    m0 = fmaxf(m0, __shfl_xor_sync(0xffffffffu, m0, 1));
    m0 = fmaxf(m0, __shfl_xor_sync(0xffffffffu, m0, 2));
    m1 = fmaxf(m1, __shfl_xor_sync(0xffffffffu, m1, 1));
    m1 = fmaxf(m1, __shfl_xor_sync(0xffffffffu, m1, 2));

    float s0 = 0.f, s1 = 0.f;
#pragma unroll
    for (int nt = 0; nt < 8; nt++) {
        sacc[nt][0] = __expf(sacc[nt][0] - m0);
        sacc[nt][1] = __expf(sacc[nt][1] - m0);
        sacc[nt][2] = __expf(sacc[nt][2] - m1);
        sacc[nt][3] = __expf(sacc[nt][3] - m1);
        s0 += sacc[nt][0] + sacc[nt][1];
        s1 += sacc[nt][2] + sacc[nt][3];
    }
    s0 += __shfl_xor_sync(0xffffffffu, s0, 1);
    s0 += __shfl_xor_sync(0xffffffffu, s0, 2);
    s1 += __shfl_xor_sync(0xffffffffu, s1, 1);
    s1 += __shfl_xor_sync(0xffffffffu, s1, 2);
    const float i0 = 1.0f / s0, i1 = 1.0f / s1;

    asm volatile("cp.async.wait_group 0;" ::: "memory");   // V ready
    __syncthreads();

    // ---- O = P V ----
    float oacc[4][4];
#pragma unroll
    for (int i = 0; i < 4; i++)
#pragma unroll
        for (int q = 0; q < 4; q++) oacc[i][q] = 0.f;

    const uint32_t vAddr = vB + ((((lane >> 3) & 1) << 3) + (lane & 7)) * 80
                              + (((lane >> 4) & 1) << 4);
#pragma unroll
    for (int kk = 0; kk < 4; kk++) {
        uint32_t pa[4];
        pa[0] = packbf2(sacc[2 * kk][0] * i0,     sacc[2 * kk][1] * i0);
        pa[1] = packbf2(sacc[2 * kk][2] * i1,     sacc[2 * kk][3] * i1);
        pa[2] = packbf2(sacc[2 * kk + 1][0] * i0, sacc[2 * kk + 1][1] * i0);
        pa[3] = packbf2(sacc[2 * kk + 1][2] * i1, sacc[2 * kk + 1][3] * i1);
        uint32_t b0, b1, b2, b3;
        ldsm4t(b0, b1, b2, b3, vAddr + kk * 16 * 80);
        { uint32_t bv0[2] = {b0, b1}, bv1[2] = {b2, b3};
          mma_bf16(oacc[0], pa, bv0); mma_bf16(oacc[1], pa, bv1); }
        ldsm4t(b0, b1, b2, b3, vAddr + kk * 16 * 80 + 32);
        { uint32_t bv0[2] = {b0, b1}, bv1[2] = {b2, b3};
          mma_bf16(oacc[2], pa, bv0); mma_bf16(oacc[3], pa, bv1); }
    }

    bf16* outB = g_attn + (size_t)w * NN * CC + h * HD;
#pragma unroll
    for (int nt = 0; nt < 4; nt++) {
        const int c = nt * 8 + ((lane & 3) << 1);
        if (v0ok)
            *(__nv_bfloat162*)&outB[(size_t)r0 * CC + c] =
                __floats2bfloat162_rn(oacc[nt][0], oacc[nt][1]);
        if (v1ok)
            *(__nv_bfloat162*)&outB[(size_t)(r0 + 8) * CC + c] =
                __floats2bfloat162_rn(oacc[nt][2], oacc[nt][3]);
    }
}

// ---------------- launch ----------------
extern "C" void kernel_launch(void* const* d_in, const int* in_sizes, int n_in,
                              void* d_out, int out_size)
{
    const float* x       = (const float*)d_in[0];
    const float* norm1_g = (const float*)d_in[1];
    const float* norm1_b = (const float*)d_in[2];
    const float* qkv_w   = (const float*)d_in[3];
    const float* qkv_b   = (const float*)d_in[4];
    const float* rel_b   = (const float*)d_in[5];
    const float* proj_w  = (const float*)d_in[6];
    const float* proj_b  = (const float*)d_in[7];
    const float* norm2_g = (const float*)d_in[8];
    const float* norm2_b = (const float*)d_in[9];
    const float* fc1_w   = (const float*)d_in[10];
    const float* fc1_b   = (const float*)d_in[11];
    const float* fc2_w   = (const float*)d_in[12];
    const float* fc2_b   = (const float*)d_in[13];
    float* out = (float*)d_out;

    bf16 *p_xw, *p_qkv, *p_attn, *p_xm, *p_h, *p_wqkv, *p_wprj, *p_wfc1, *p_wfc2;
    float *p_y;
    cudaGetSymbolAddress((void**)&p_xw,   g_xw);
    cudaGetSymbolAddress((void**)&p_qkv,  g_qkv);
    cudaGetSymbolAddress((void**)&p_attn, g_attn);
    cudaGetSymbolAddress((void**)&p_y,    g_y);
    cudaGetSymbolAddress((void**)&p_xm,   g_xm);
    cudaGetSymbolAddress((void**)&p_h,    g_h);
    cudaGetSymbolAddress((void**)&p_wqkv, g_wqkv);
    cudaGetSymbolAddress((void**)&p_wprj, g_wprj);
    cudaGetSymbolAddress((void**)&p_wfc1, g_wfc1);
    cudaGetSymbolAddress((void**)&p_wfc2, g_wfc2);

    cudaFuncSetAttribute(gemm_bf16<0, 0, true>,  cudaFuncAttributeMaxDynamicSharedMemorySize, G_SMEM);
    cudaFuncSetAttribute(gemm_bf16<0, 2, false>, cudaFuncAttributeMaxDynamicSharedMemorySize, G_SMEM);
    cudaFuncSetAttribute(gemm_bf16<1, 0, true>,  cudaFuncAttributeMaxDynamicSharedMemorySize, G_SMEM);
    cudaFuncSetAttribute(gemm_bf16<0, 1, false>, cudaFuncAttributeMaxDynamicSharedMemorySize, G_SMEM);

    // 0) merged prep (weights + tables + LN1)
    prep_kernel<<<456 + TOK / 8, 256>>>(qkv_w, proj_w, fc1_w, fc2_w, rel_b,
                                        x, norm1_g, norm1_b);

    // 1) QKV gemm [TOK,192]x[192,576] -> bf16
    gemm_bf16<0, 0, true><<<dim3(576 / 64, TOK / 128), 128, G_SMEM>>>(
        p_xw, p_wqkv, qkv_b, nullptr, p_qkv, TOK, 3 * CC, CC);

    // 2) tensor-core windowed attention (2 heads / block)
    attn_mma_kernel<<<(TOK / NN) * 3, 256>>>();

    // 3) proj gemm + window-reverse/unshift scatter + residual -> g_y (fp32)
    gemm_bf16<0, 2, false><<<dim3(192 / 64, TOK / 128), 128, G_SMEM>>>(
        p_attn, p_wprj, proj_b, x, p_y, TOK, CC, CC);

    // 4) LN2 (bf16)
    ln2_kernel<<<TOK / 8, 256>>>(norm2_g, norm2_b);

    // 5) fc1 + exact GELU [TOK,192]x[192,768] -> bf16
    gemm_bf16<1, 0, true><<<dim3(HIDD / 64, TOK / 128), 128, G_SMEM>>>(
        p_xm, p_wfc1, fc1_b, nullptr, p_h, TOK, HIDD, CC);

    // 6) fc2 + residual [TOK,768]x[768,192] -> d_out (fp32)
    gemm_bf16<0, 1, false><<<dim3(192 / 64, TOK / 128), 128, G_SMEM>>>(
        p_h, p_wfc2, fc2_b, p_y, out, TOK, CC, HIDD);
}